// round 1
// baseline (speedup 1.0000x reference)
#include <cuda_runtime.h>

// Bilinear resample: out[b,h,w] = bilinear(imgs[b], (w+dx, h+dy)) with
// zero-padding for out-of-bounds corners.
// imgs: (B,1024,1024,1) f32, dvfs: (B,1024,1024,2) f32, out: (B,1024,1024,1) f32.
//
// HBM-bound: ~512MB total traffic. Each thread handles 2 adjacent pixels in a
// row -> one float4 dvfs load, one float2 store, gathers hit L1/L2 (offsets ~N(0,1)).

#define HH 1024
#define WW 1024
#define HW (HH * WW)

__device__ __forceinline__ float bilin_one(const float* __restrict__ img,
                                           int h, int w, float dx, float dy) {
    float fx = (float)w + dx;
    float fy = (float)h + dy;
    float x0f = floorf(fx);
    float y0f = floorf(fy);
    float wx = fx - x0f;
    float wy = fy - y0f;
    int x0 = (int)x0f;
    int y0 = (int)y0f;
    int x1 = x0 + 1;
    int y1 = y0 + 1;

    bool vx0 = (x0 >= 0) & (x0 < WW);
    bool vx1 = (x1 >= 0) & (x1 < WW);
    bool vy0 = (y0 >= 0) & (y0 < HH);
    bool vy1 = (y1 >= 0) & (y1 < HH);

    float v00 = 0.f, v01 = 0.f, v10 = 0.f, v11 = 0.f;
    if (vy0) {
        const float* row = img + y0 * WW;
        if (vx0) v00 = __ldg(row + x0);
        if (vx1) v01 = __ldg(row + x1);
    }
    if (vy1) {
        const float* row = img + y1 * WW;
        if (vx0) v10 = __ldg(row + x0);
        if (vx1) v11 = __ldg(row + x1);
    }

    float omx = 1.0f - wx;
    float omy = 1.0f - wy;
    return v00 * omx * omy + v01 * wx * omy + v10 * omx * wy + v11 * wx * wy;
}

__global__ void __launch_bounds__(256)
bilinear_kernel(const float* __restrict__ imgs,
                const float* __restrict__ dvfs,
                float* __restrict__ out,
                int n_pairs) {
    int t = blockIdx.x * blockDim.x + threadIdx.x;
    if (t >= n_pairs) return;

    int idx = t * 2;                       // first pixel of the pair
    int w = idx & (WW - 1);                // even, so w and w+1 share a row
    int h = (idx >> 10) & (HH - 1);
    int b = idx >> 20;

    const float* img = imgs + b * HW;

    // dvfs packed (x,y) interleaved: pixels idx, idx+1 -> 4 floats, 16B aligned
    float4 d = *reinterpret_cast<const float4*>(dvfs + (size_t)idx * 2);

    float r0 = bilin_one(img, h, w,     d.x, d.y);
    float r1 = bilin_one(img, h, w + 1, d.z, d.w);

    *reinterpret_cast<float2*>(out + idx) = make_float2(r0, r1);
}

extern "C" void kernel_launch(void* const* d_in, const int* in_sizes, int n_in,
                              void* d_out, int out_size) {
    const float* imgs = (const float*)d_in[0];
    const float* dvfs = (const float*)d_in[1];
    float* out = (float*)d_out;

    int total = out_size;          // B*H*W
    int n_pairs = total / 2;
    int threads = 256;
    int blocks = (n_pairs + threads - 1) / threads;
    bilinear_kernel<<<blocks, threads>>>(imgs, dvfs, out, n_pairs);
}